// round 9
// baseline (speedup 1.0000x reference)
#include <cuda_runtime.h>
#include <cuda_bf16.h>

#define NJ 24
#define NJP 12            // joint pairs
#define EPSF 1e-6f

typedef unsigned long long ull;

// ---- packed f32x2 helpers (sm_103a) ----
__device__ __forceinline__ ull f2_fma(ull a, ull b, ull c) {
    ull d; asm("fma.rn.f32x2 %0, %1, %2, %3;" : "=l"(d) : "l"(a), "l"(b), "l"(c)); return d;
}
__device__ __forceinline__ ull f2_mul(ull a, ull b) {
    ull d; asm("mul.rn.f32x2 %0, %1, %2;" : "=l"(d) : "l"(a), "l"(b)); return d;
}
__device__ __forceinline__ ull f2_add(ull a, ull b) {
    ull d; asm("add.rn.f32x2 %0, %1, %2;" : "=l"(d) : "l"(a), "l"(b)); return d;
}
__device__ __forceinline__ ull f2_pack(float lo, float hi) {
    ull d;
    asm("mov.b64 %0, {%1, %2};" : "=l"(d) : "r"(__float_as_uint(lo)), "r"(__float_as_uint(hi)));
    return d;
}
__device__ __forceinline__ void f2_unpack(ull a, float& lo, float& hi) {
    unsigned int l, h;
    asm("mov.b64 {%0, %1}, %2;" : "=r"(l), "=r"(h) : "l"(a));
    lo = __uint_as_float(l); hi = __uint_as_float(h);
}
__device__ __forceinline__ float sqrt_ap(float x) {
    float r; asm("sqrt.approx.f32 %0, %1;" : "=f"(r) : "f"(x)); return r;
}
__device__ __forceinline__ float rcp_ap(float x) {
    float r; asm("rcp.approx.f32 %0, %1;" : "=f"(r) : "f"(x)); return r;
}

// Per-joint preprocessed constants, k = 0..23:
//  0..11 : transform rows 0..2 (m00..m23)
// 12..14 : loc (lx,ly,lz)
// 15     : a0' = C0*f0 + 0.5 - C2c*f6
// 16..18 : a1=-C1*f1, a2=C1*f2, a3=-C1*f3
// 19..23 : a4=B*f4, a5=-B*f5, b6=3*C2c*f6, a7=-B*f7, a8=D*f8
__device__ __forceinline__ float joint_const(int j, int k,
                                             const float* __restrict__ transforms,
                                             const float* __restrict__ sh_feats,
                                             const float* __restrict__ locs)
{
    const float coef0 = 0.28209479177387814f;
    const float coefA = 0.4886025119029199f;
    const float coefB = 1.0925484305920792f;
    const float coefC = 0.31539156525252005f;
    const float coefD = 0.5462742152960396f;
    if (k < 12)  return transforms[j * 16 + k];
    if (k < 15)  return locs[j * 3 + (k - 12)];
    if (k == 15) return coef0 * sh_feats[j * 9 + 0] + 0.5f - coefC * sh_feats[j * 9 + 6];
    if (k == 16) return -coefA * sh_feats[j * 9 + 1];
    if (k == 17) return  coefA * sh_feats[j * 9 + 2];
    if (k == 18) return -coefA * sh_feats[j * 9 + 3];
    if (k == 19) return  coefB * sh_feats[j * 9 + 4];
    if (k == 20) return -coefB * sh_feats[j * 9 + 5];
    if (k == 21) return 3.0f * coefC * sh_feats[j * 9 + 6];
    if (k == 22) return -coefB * sh_feats[j * 9 + 7];
    return coefD * sh_feats[j * 9 + 8];
}

// Shared: per joint-PAIR jp (joints 2jp, 2jp+1), 24 packed {c_j0, c_j1} values
// = 12 ulonglong2 per pair iteration (6 LDS.128 per joint).
__global__ __launch_bounds__(256)
void shCaster_kernel(const float* __restrict__ xyz,
                     const float* __restrict__ vdir,
                     const float* __restrict__ transforms,
                     const float* __restrict__ sh_feats,
                     const float* __restrict__ locs,
                     float* __restrict__ out,
                     int n)
{
    __shared__ __align__(16) ull S2[NJP * 24];

    for (int idx = threadIdx.x; idx < NJP * 24; idx += blockDim.x) {
        int jp = idx / 24, k = idx % 24;
        float va = joint_const(2 * jp,     k, transforms, sh_feats, locs);
        float vb = joint_const(2 * jp + 1, k, transforms, sh_feats, locs);
        S2[idx] = ((ull)__float_as_uint(vb) << 32) | __float_as_uint(va);  // {lo=j0, hi=j1}
    }
    __syncthreads();

    int i = blockIdx.x * blockDim.x + threadIdx.x;
    if (i >= n) return;

    const float x = __ldg(&xyz[3 * i]);
    const float y = __ldg(&xyz[3 * i + 1]);
    const float z = __ldg(&xyz[3 * i + 2]);
    const float vx = __ldg(&vdir[3 * i]);
    const float vy = __ldg(&vdir[3 * i + 1]);
    const float vz = __ldg(&vdir[3 * i + 2]);

    const ull x2  = f2_pack(x, x);
    const ull y2  = f2_pack(y, y);
    const ull z2  = f2_pack(z, z);
    const ull vx2 = f2_pack(vx, vx);
    const ull vy2 = f2_pack(vy, vy);
    const ull vz2 = f2_pack(vz, vz);
    const ull NEG1 = f2_pack(-1.f, -1.f);

    ull wsum2 = 0ull;
    ull ox2 = 0ull, oy2 = 0ull, oz2 = 0ull;   // sum w * p     (per joint half)
    ull rx2 = 0ull, ry2 = 0ull, rz2 = 0ull;   // sum w * (R v)

    const ulonglong2* __restrict__ Cbase = reinterpret_cast<const ulonglong2*>(S2);

#pragma unroll 4
    for (int jp = 0; jp < NJP; ++jp) {
        const ulonglong2* C = Cbase + jp * 12;
        const ulonglong2 c0 = C[0];   // m00 | m01   (each = {j0,j1})
        const ulonglong2 c1 = C[1];   // m02 | m03
        const ulonglong2 c2 = C[2];   // m10 | m11
        const ulonglong2 c3 = C[3];   // m12 | m13
        const ulonglong2 c4 = C[4];   // m20 | m21
        const ulonglong2 c5 = C[5];   // m22 | m23
        const ulonglong2 c6 = C[6];   // lx  | ly
        const ulonglong2 c7 = C[7];   // lz  | a0'
        const ulonglong2 c8 = C[8];   // a1  | a2
        const ulonglong2 c9 = C[9];   // a3  | a4
        const ulonglong2 cA = C[10];  // a5  | b6
        const ulonglong2 cB = C[11];  // a7  | a8

        // p = (M [x,1])[:3] for both joints at once
        ull px = f2_fma(c0.x, x2, f2_fma(c0.y, y2, f2_fma(c1.x, z2, c1.y)));
        ull py = f2_fma(c2.x, x2, f2_fma(c2.y, y2, f2_fma(c3.x, z2, c3.y)));
        ull pz = f2_fma(c4.x, x2, f2_fma(c4.y, y2, f2_fma(c5.x, z2, c5.y)));

        // R v for both joints
        ull Rx = f2_fma(c0.x, vx2, f2_fma(c0.y, vy2, f2_mul(c1.x, vz2)));
        ull Ry = f2_fma(c2.x, vx2, f2_fma(c2.y, vy2, f2_mul(c3.x, vz2)));
        ull Rz = f2_fma(c4.x, vx2, f2_fma(c4.y, vy2, f2_mul(c5.x, vz2)));

        // d = loc - p
        ull dx = f2_fma(px, NEG1, c6.x);
        ull dy = f2_fma(py, NEG1, c6.y);
        ull dz = f2_fma(pz, NEG1, c7.x);

        ull sx = f2_mul(dx, dx);
        ull sy = f2_mul(dy, dy);
        ull sz = f2_mul(dz, dz);
        ull n2 = f2_add(f2_add(sx, sy), sz);

        // linear SH on d
        ull L = f2_fma(c8.x, dy, f2_fma(c8.y, dz, f2_mul(c9.x, dx)));

        // quadratic SH on d
        ull Q = f2_mul(c9.y, f2_mul(dx, dy));
        Q = f2_fma(cA.x, f2_mul(dy, dz), Q);
        Q = f2_fma(cA.y, sz, Q);
        Q = f2_fma(cB.x, f2_mul(dx, dz), Q);
        Q = f2_fma(cB.y, f2_fma(sy, NEG1, sx), Q);

        // s = sqrt(n2) per lane (lanes = two joints)
        float n2a, n2b; f2_unpack(n2, n2a, n2b);
        ull s2 = f2_pack(sqrt_ap(n2a), sqrt_ap(n2b));

        // denom = rad*n2 = a0'*n2 + L*s + Q ; numer = n2*s
        ull denom = f2_fma(c7.y, n2, Q);
        denom = f2_fma(L, s2, denom);
        ull tt = f2_fma(f2_mul(n2, s2), NEG1, denom);   // denom - numer

        // w = relu(denom-numer)/denom per joint
        float ta, tb; f2_unpack(tt, ta, tb);
        float da, db; f2_unpack(denom, da, db);
        float wa = fmaxf(ta, 0.f) * rcp_ap(fmaxf(da, 1e-30f));
        float wb = fmaxf(tb, 0.f) * rcp_ap(fmaxf(db, 1e-30f));
        ull w2 = f2_pack(wa, wb);

        wsum2 = f2_add(wsum2, w2);
        ox2 = f2_fma(w2, px, ox2);
        oy2 = f2_fma(w2, py, oy2);
        oz2 = f2_fma(w2, pz, oz2);
        rx2 = f2_fma(w2, Rx, rx2);
        ry2 = f2_fma(w2, Ry, ry2);
        rz2 = f2_fma(w2, Rz, rz2);
    }

    // horizontal reduce over the two joint lanes
    float wsa, wsb; f2_unpack(wsum2, wsa, wsb);
    float oxa, oxb; f2_unpack(ox2, oxa, oxb);
    float oya, oyb; f2_unpack(oy2, oya, oyb);
    float oza, ozb; f2_unpack(oz2, oza, ozb);
    float rxa, rxb; f2_unpack(rx2, rxa, rxb);
    float rya, ryb; f2_unpack(ry2, rya, ryb);
    float rza, rzb; f2_unpack(rz2, rza, rzb);

    float wsum = wsa + wsb;
    float ox = oxa + oxb, oy = oya + oyb, oz = oza + ozb;
    float rx = rxa + rxb, ry = rya + ryb, rz = rza + rzb;

    float* outv = out + (size_t)3 * n;

    if (wsum > EPSF) {
        float inv = rcp_ap(wsum);
        out[3 * i]     = ox * inv;
        out[3 * i + 1] = oy * inv;
        out[3 * i + 2] = oz * inv;
        outv[3 * i]     = rx * inv;
        outv[3 * i + 1] = ry * inv;
        outv[3 * i + 2] = rz * inv;
    } else {
        out[3 * i]     = x;
        out[3 * i + 1] = y;
        out[3 * i + 2] = z;
        outv[3 * i]     = vx;
        outv[3 * i + 1] = vy;
        outv[3 * i + 2] = vz;
    }
}

extern "C" void kernel_launch(void* const* d_in, const int* in_sizes, int n_in,
                              void* d_out, int out_size) {
    const float* xyz        = (const float*)d_in[0];
    const float* viewdirs   = (const float*)d_in[1];
    const float* transforms = (const float*)d_in[2];
    // d_in[3] = ray_valid — unused
    const float* sh_feats   = (const float*)d_in[4];
    const float* locs       = (const float*)d_in[5];
    float* out = (float*)d_out;

    int n = in_sizes[0] / 3;      // 524288
    int threads = 256;
    int blocks = (n + threads - 1) / threads;
    shCaster_kernel<<<blocks, threads>>>(xyz, viewdirs, transforms, sh_feats,
                                         locs, out, n);
}

// round 10
// speedup vs baseline: 1.1104x; 1.1104x over previous
#include <cuda_runtime.h>
#include <cuda_bf16.h>

#define NJ 24
#define EPSF 1e-6f

typedef unsigned long long ull;

// ---- packed f32x2 helpers (sm_103a) ----
__device__ __forceinline__ ull f2_fma(ull a, ull b, ull c) {
    ull d; asm("fma.rn.f32x2 %0, %1, %2, %3;" : "=l"(d) : "l"(a), "l"(b), "l"(c)); return d;
}
__device__ __forceinline__ ull f2_mul(ull a, ull b) {
    ull d; asm("mul.rn.f32x2 %0, %1, %2;" : "=l"(d) : "l"(a), "l"(b)); return d;
}
__device__ __forceinline__ ull f2_add(ull a, ull b) {
    ull d; asm("add.rn.f32x2 %0, %1, %2;" : "=l"(d) : "l"(a), "l"(b)); return d;
}
__device__ __forceinline__ ull f2_pack(float lo, float hi) {
    ull d;
    asm("mov.b64 %0, {%1, %2};" : "=l"(d) : "r"(__float_as_uint(lo)), "r"(__float_as_uint(hi)));
    return d;
}
__device__ __forceinline__ void f2_unpack(ull a, float& lo, float& hi) {
    unsigned int l, h;
    asm("mov.b64 {%0, %1}, %2;" : "=r"(l), "=r"(h) : "l"(a));
    lo = __uint_as_float(l); hi = __uint_as_float(h);
}
__device__ __forceinline__ float sqrt_ap(float x) {
    float r; asm("sqrt.approx.f32 %0, %1;" : "=f"(r) : "f"(x)); return r;
}
__device__ __forceinline__ float rcp_ap(float x) {
    float r; asm("rcp.approx.f32 %0, %1;" : "=f"(r) : "f"(x)); return r;
}

// Shared layout per joint: 24 constants duplicated as {c,c} pairs (12 ulonglong2):
//  pairs 0..5 : transform rows (m00 m01 | m02 m03 | m10 m11 | m12 m13 | m20 m21 | m22 m23)
//  pair  6,7  : lx ly | lz a0'     a0' = C0*f0 + 0.5 - C2c*f6
//  pair  8,9  : a1 a2 | a3 a4      a1=-C1*f1, a2=C1*f2, a3=-C1*f3, a4=B*f4
//  pair 10,11 : a5 b6 | a7 a8      a5=-B*f5, b6=3*C2c*f6, a7=-B*f7, a8=D*f8

__global__ __launch_bounds__(256)
void shCaster_kernel(const float* __restrict__ xyz,
                     const float* __restrict__ vdir,
                     const float* __restrict__ transforms,
                     const float* __restrict__ sh_feats,
                     const float* __restrict__ locs,
                     float* __restrict__ out,
                     int half, int n)
{
    __shared__ __align__(16) ull S2[NJ * 24];

    {
        const float coef0 = 0.28209479177387814f;
        const float coefA = 0.4886025119029199f;
        const float coefB = 1.0925484305920792f;
        const float coefC = 0.31539156525252005f;
        const float coefD = 0.5462742152960396f;
        for (int idx = threadIdx.x; idx < NJ * 24; idx += blockDim.x) {
            int j = idx / 24, k = idx % 24;
            float v;
            if (k < 12) {
                v = transforms[j * 16 + k];
            } else if (k < 15) {
                v = locs[j * 3 + (k - 12)];
            } else if (k == 15) {
                v = coef0 * sh_feats[j * 9 + 0] + 0.5f - coefC * sh_feats[j * 9 + 6];
            } else if (k == 16) {
                v = -coefA * sh_feats[j * 9 + 1];
            } else if (k == 17) {
                v =  coefA * sh_feats[j * 9 + 2];
            } else if (k == 18) {
                v = -coefA * sh_feats[j * 9 + 3];
            } else if (k == 19) {
                v =  coefB * sh_feats[j * 9 + 4];
            } else if (k == 20) {
                v = -coefB * sh_feats[j * 9 + 5];
            } else if (k == 21) {
                v = 3.0f * coefC * sh_feats[j * 9 + 6];
            } else if (k == 22) {
                v = -coefB * sh_feats[j * 9 + 7];
            } else {
                v =  coefD * sh_feats[j * 9 + 8];
            }
            unsigned int b = __float_as_uint(v);
            S2[j * 24 + k] = ((ull)b << 32) | b;
        }
    }
    __syncthreads();

    int t = blockIdx.x * blockDim.x + threadIdx.x;
    if (t >= half) return;
    int i0 = t, i1 = t + half;

    const ull x2  = f2_pack(__ldg(&xyz[3 * i0]),     __ldg(&xyz[3 * i1]));
    const ull y2  = f2_pack(__ldg(&xyz[3 * i0 + 1]), __ldg(&xyz[3 * i1 + 1]));
    const ull z2  = f2_pack(__ldg(&xyz[3 * i0 + 2]), __ldg(&xyz[3 * i1 + 2]));
    const ull vx2 = f2_pack(__ldg(&vdir[3 * i0]),     __ldg(&vdir[3 * i1]));
    const ull vy2 = f2_pack(__ldg(&vdir[3 * i0 + 1]), __ldg(&vdir[3 * i1 + 1]));
    const ull vz2 = f2_pack(__ldg(&vdir[3 * i0 + 2]), __ldg(&vdir[3 * i1 + 2]));

    const ull NEG1 = f2_pack(-1.f, -1.f);

    ull wsum2 = 0ull;
    ull ox2 = 0ull, oy2 = 0ull, oz2 = 0ull;   // sum w * p
    ull rx2 = 0ull, ry2 = 0ull, rz2 = 0ull;   // sum w * (R v)

#pragma unroll
    for (int j = 0; j < NJ; ++j) {
        const ulonglong2* C = reinterpret_cast<const ulonglong2*>(S2 + j * 24);
        const ulonglong2 c0 = C[0];
        const ulonglong2 c1 = C[1];
        const ulonglong2 c2 = C[2];
        const ulonglong2 c3 = C[3];
        const ulonglong2 c4 = C[4];
        const ulonglong2 c5 = C[5];
        const ulonglong2 c6 = C[6];
        const ulonglong2 c7 = C[7];
        const ulonglong2 c8 = C[8];
        const ulonglong2 c9 = C[9];
        const ulonglong2 cA = C[10];
        const ulonglong2 cB = C[11];

        // p = (M [x,1])[:3]
        ull px = f2_fma(c0.x, x2, f2_fma(c0.y, y2, f2_fma(c1.x, z2, c1.y)));
        ull py = f2_fma(c2.x, x2, f2_fma(c2.y, y2, f2_fma(c3.x, z2, c3.y)));
        ull pz = f2_fma(c4.x, x2, f2_fma(c4.y, y2, f2_fma(c5.x, z2, c5.y)));

        // R v
        ull Rx = f2_fma(c0.x, vx2, f2_fma(c0.y, vy2, f2_mul(c1.x, vz2)));
        ull Ry = f2_fma(c2.x, vx2, f2_fma(c2.y, vy2, f2_mul(c3.x, vz2)));
        ull Rz = f2_fma(c4.x, vx2, f2_fma(c4.y, vy2, f2_mul(c5.x, vz2)));

        // d = loc - p
        ull dx = f2_fma(px, NEG1, c6.x);
        ull dy = f2_fma(py, NEG1, c6.y);
        ull dz = f2_fma(pz, NEG1, c7.x);

        ull sx = f2_mul(dx, dx);
        ull sy = f2_mul(dy, dy);
        ull sz = f2_mul(dz, dz);
        ull n2 = f2_add(f2_add(sx, sy), sz);

        // linear SH on d
        ull L = f2_fma(c8.x, dy, f2_fma(c8.y, dz, f2_mul(c9.x, dx)));

        // quadratic SH on d
        ull Q = f2_mul(c9.y, f2_mul(dx, dy));
        Q = f2_fma(cA.x, f2_mul(dy, dz), Q);
        Q = f2_fma(cA.y, sz, Q);
        Q = f2_fma(cB.x, f2_mul(dx, dz), Q);
        Q = f2_fma(cB.y, f2_fma(sy, NEG1, sx), Q);

        // s = sqrt(n2) per lane
        float n2a, n2b; f2_unpack(n2, n2a, n2b);
        ull s2 = f2_pack(sqrt_ap(n2a), sqrt_ap(n2b));

        // denom = rad*n2 = a0'*n2 + L*s + Q ; numer = n2*s
        ull denom = f2_fma(c7.y, n2, Q);
        denom = f2_fma(L, s2, denom);
        ull tt = f2_fma(f2_mul(n2, s2), NEG1, denom);   // denom - numer

        // w = relu(denom-numer)/denom  (zero whenever rad <= 0)
        float ta, tb; f2_unpack(tt, ta, tb);
        float da, db; f2_unpack(denom, da, db);
        float wa = fmaxf(ta, 0.f) * rcp_ap(fmaxf(da, 1e-30f));
        float wb = fmaxf(tb, 0.f) * rcp_ap(fmaxf(db, 1e-30f));
        ull w2 = f2_pack(wa, wb);

        wsum2 = f2_add(wsum2, w2);
        ox2 = f2_fma(w2, px, ox2);
        oy2 = f2_fma(w2, py, oy2);
        oz2 = f2_fma(w2, pz, oz2);
        rx2 = f2_fma(w2, Rx, rx2);
        ry2 = f2_fma(w2, Ry, ry2);
        rz2 = f2_fma(w2, Rz, rz2);
    }

    // ---- epilogue per lane ----
    float wsa, wsb;  f2_unpack(wsum2, wsa, wsb);
    float oxa, oxb;  f2_unpack(ox2, oxa, oxb);
    float oya, oyb;  f2_unpack(oy2, oya, oyb);
    float oza, ozb;  f2_unpack(oz2, oza, ozb);
    float rxa, rxb;  f2_unpack(rx2, rxa, rxb);
    float rya, ryb;  f2_unpack(ry2, rya, ryb);
    float rza, rzb;  f2_unpack(rz2, rza, rzb);

    float xa, xb, ya, yb, za, zb, vxa, vxb, vya, vyb, vza, vzb;
    f2_unpack(x2, xa, xb);   f2_unpack(y2, ya, yb);   f2_unpack(z2, za, zb);
    f2_unpack(vx2, vxa, vxb); f2_unpack(vy2, vya, vyb); f2_unpack(vz2, vza, vzb);

    float* outv = out + (size_t)3 * n;

    if (wsa > EPSF) {
        float inv = rcp_ap(wsa);
        out[3 * i0] = oxa * inv;  out[3 * i0 + 1] = oya * inv;  out[3 * i0 + 2] = oza * inv;
        outv[3 * i0] = rxa * inv; outv[3 * i0 + 1] = rya * inv; outv[3 * i0 + 2] = rza * inv;
    } else {
        out[3 * i0] = xa;  out[3 * i0 + 1] = ya;  out[3 * i0 + 2] = za;
        outv[3 * i0] = vxa; outv[3 * i0 + 1] = vya; outv[3 * i0 + 2] = vza;
    }
    if (wsb > EPSF) {
        float inv = rcp_ap(wsb);
        out[3 * i1] = oxb * inv;  out[3 * i1 + 1] = oyb * inv;  out[3 * i1 + 2] = ozb * inv;
        outv[3 * i1] = rxb * inv; outv[3 * i1 + 1] = ryb * inv; outv[3 * i1 + 2] = rzb * inv;
    } else {
        out[3 * i1] = xb;  out[3 * i1 + 1] = yb;  out[3 * i1 + 2] = zb;
        outv[3 * i1] = vxb; outv[3 * i1 + 1] = vyb; outv[3 * i1 + 2] = vzb;
    }
}

extern "C" void kernel_launch(void* const* d_in, const int* in_sizes, int n_in,
                              void* d_out, int out_size) {
    const float* xyz        = (const float*)d_in[0];
    const float* viewdirs   = (const float*)d_in[1];
    const float* transforms = (const float*)d_in[2];
    // d_in[3] = ray_valid — unused
    const float* sh_feats   = (const float*)d_in[4];
    const float* locs       = (const float*)d_in[5];
    float* out = (float*)d_out;

    int n = in_sizes[0] / 3;      // 524288
    int half = n / 2;             // 262144
    int threads = 256;
    int blocks = (half + threads - 1) / threads;
    shCaster_kernel<<<blocks, threads>>>(xyz, viewdirs, transforms, sh_feats,
                                         locs, out, half, n);
}